// round 17
// baseline (speedup 1.0000x reference)
#include <cuda_runtime.h>
#include <cuda_fp16.h>
#include <cstdint>

#define NN 50000
#define IC 256
#define DD 128
#define NH 8
#define HDIM 1024

#define TM 64                         // M tile
#define NTILES ((NN + TM - 1) / TM)   // 782

#define AROWB 80                      // bytes per A row in packed image (32 halves + pad)
#define ACHUNKB (TM * AROWB)          // 5120 B per (tile, chunk)
#define ATILEB (8 * ACHUNKB)          // 40960 B per tile

// Device scratch (allocation-free per harness rules)
__device__ __half g_Wph[IC * DD];                    // fragment-packed fp16 weight (64KB)
__device__ float  g_bm[DD];                          // mean-over-heads V bias
__device__ uint4  g_Xh[NTILES * ATILEB / 16];        // pre-tiled fp16 X image (~32MB)

__device__ __forceinline__ uint32_t smem_to_u32(const void* p) {
    uint32_t a;
    asm("{ .reg .u64 t; cvta.to.shared.u64 t, %1; cvt.u32.u64 %0, t; }" : "=r"(a) : "l"(p));
    return a;
}

// mma.sync m16n8k16 fp16 (HMMA.16816 on sm_103), fp32 accumulate
__device__ __forceinline__ void mma_f16(float* d, const uint32_t* a, const uint32_t* b) {
    asm volatile(
        "mma.sync.aligned.m16n8k16.row.col.f32.f16.f16.f32 "
        "{%0,%1,%2,%3}, {%4,%5,%6,%7}, {%8,%9}, {%0,%1,%2,%3};"
        : "+f"(d[0]), "+f"(d[1]), "+f"(d[2]), "+f"(d[3])
        : "r"(a[0]), "r"(a[1]), "r"(a[2]), "r"(a[3]), "r"(b[0]), "r"(b[1]));
}

__device__ __forceinline__ void ldsm_x4(uint32_t* a, uint32_t addr) {
    asm volatile("ldmatrix.sync.aligned.m8n8.x4.shared.b16 {%0,%1,%2,%3}, [%4];"
                 : "=r"(a[0]), "=r"(a[1]), "=r"(a[2]), "=r"(a[3]) : "r"(addr));
}

__device__ __forceinline__ void lds128(uint32_t* r, uint32_t addr) {
    asm volatile("ld.shared.v4.u32 {%0,%1,%2,%3}, [%4];"
                 : "=r"(r[0]), "=r"(r[1]), "=r"(r[2]), "=r"(r[3]) : "r"(addr));
}

// ---------- prep: fragment-pack fp16(mean_h Wv) with baked SW128; mean bias ----------
// (identical layout to Round 16 — passed)
__global__ void prep_kernel(const float* __restrict__ Wv, const float* __restrict__ bv) {
    int e = blockIdx.x * 256 + threadIdx.x;     // 0..32767
    int k = e >> 7, d = e & 127;
    float s = 0.f;
#pragma unroll
    for (int h = 0; h < NH; h++) s += Wv[(size_t)k * HDIM + h * DD + d];
    __half hv = __float2half_rn(s * 0.125f);

    int c = k >> 5, kk = k & 31, s16 = kk >> 4, kl = kk & 15;
    int lane = ((d & 7) << 2) | ((kl & 7) >> 1);
    int pos = ((kl >> 3) & 1) * 2 + (kl & 1);
    int jn = (d >> 3) & 3, wn = d >> 5;
    int inner = lane * 32 + jn * 8 + pos * 2;
    int sw = inner ^ ((inner >> 3) & 0x70);
    g_Wph[(c * 8192 + wn * 2048 + s16 * 1024 + sw) >> 1] = hv;

    if (e < DD) {
        float b = 0.f;
#pragma unroll
        for (int h = 0; h < NH; h++) b += bv[h * DD + e];
        g_bm[e] = b * 0.125f;
    }
}

// ---------- convA: X fp32 -> pre-tiled fp16 image ----------
// thread e = (tile<<11) | (chunk<<8) | (row<<2) | q   handles 8 halves (16B)
// dst byte addr = tile*ATILEB + chunk*ACHUNKB + row*AROWB + q*16
__global__ __launch_bounds__(256) void convA(const float* __restrict__ X) {
    int e = blockIdx.x * 256 + threadIdx.x;
    int tile = e >> 11;
    int rem = e & 2047;
    int c = rem >> 8, r = (rem >> 2) & 63, q = rem & 3;
    int gr = tile * TM + r;
    int grc = (gr < NN) ? gr : (NN - 1);
    const float4* s = (const float4*)(X + (size_t)grc * IC + c * 32 + q * 8);
    float4 f0 = s[0], f1 = s[1];
    __half2 h0 = __floats2half2_rn(f0.x, f0.y);
    __half2 h1 = __floats2half2_rn(f0.z, f0.w);
    __half2 h2 = __floats2half2_rn(f1.x, f1.y);
    __half2 h3 = __floats2half2_rn(f1.z, f1.w);
    uint4 o;
    o.x = *(uint32_t*)&h0; o.y = *(uint32_t*)&h1;
    o.z = *(uint32_t*)&h2; o.w = *(uint32_t*)&h3;
    g_Xh[(tile * ATILEB + c * ACHUNKB + r * AROWB + q * 16) >> 4] = o;
}

// ---------- GEMM: out = fp16(X) @ fp16(Wm) + bm ----------
// 782 CTAs, tile 64x128, 8 warps 2(M)x4(N), 4 CTAs/SM.
// RS=4 ring; A and W both pure cp.async (L1 bypass), zero register staging.
#define WBYTES 8192
#define STB (ACHUNKB + WBYTES)         // 13312
#define RS 4
#define VSMEM (RS * STB)               // 53248 -> 4 CTAs/SM (213KB)

__device__ __forceinline__ void issue_chunk(uint32_t smBase, int tile, int c, int tid) {
    const uint32_t st = smBase + (c % RS) * STB;
    const char* asrc = (const char*)g_Xh + tile * ATILEB + c * ACHUNKB;
    // A: 5120 B = 320 x 16B
#pragma unroll
    for (int i = 0; i < 2; i++) {
        int idx = tid + i * 256;
        if (idx < 320) {
            asm volatile("cp.async.cg.shared.global [%0], [%1], 16;"
                         :: "r"(st + idx * 16), "l"(asrc + idx * 16));
        }
    }
    // W: 8192 B = 512 x 16B
    const char* wsrc = (const char*)g_Wph + c * 8192;
#pragma unroll
    for (int i = 0; i < 2; i++) {
        int idx = tid + i * 256;
        asm volatile("cp.async.cg.shared.global [%0], [%1], 16;"
                     :: "r"(st + ACHUNKB + idx * 16), "l"(wsrc + idx * 16));
    }
}

__global__ __launch_bounds__(256, 4) void vmean_gemm(float* __restrict__ out) {
    extern __shared__ char smc[];
    const uint32_t smBase = smem_to_u32(smc);

    const int tid = threadIdx.x;
    const int lane = tid & 31;
    const int wid = tid >> 5;
    const int warpM = wid >> 2;      // 0..1 (32 rows each)
    const int warpN = wid & 3;       // 0..3 (32 cols each)
    const int tile = blockIdx.x;
    const int m0 = tile * TM;

    // ldmatrix lane offsets (bytes, rel. to stage A base)
    const int rloc = lane & 15;
    const int khalf = (lane >> 4) << 4;    // 0 or 16 bytes
    uint32_t aRel[2];
#pragma unroll
    for (int mt = 0; mt < 2; mt++)
        aRel[mt] = (warpM * 32 + mt * 16 + rloc) * AROWB + khalf;

    // B smem read offset (swizzled), rel. to stage W base
    const uint32_t bRel = (uint32_t)(warpN * 2048 + ((lane * 32) ^ (((lane >> 2) & 7) << 4)));

    // prologue: chunks 0,1,2
#pragma unroll
    for (int g = 0; g < RS - 1; g++) {
        issue_chunk(smBase, tile, g, tid);
        asm volatile("cp.async.commit_group;");
    }

    float acc[2][4][4];
#pragma unroll
    for (int mt = 0; mt < 2; mt++)
#pragma unroll
        for (int jn = 0; jn < 4; jn++)
#pragma unroll
            for (int v = 0; v < 4; v++) acc[mt][jn][v] = 0.f;

#pragma unroll
    for (int g = 0; g < 8; g++) {
        asm volatile("cp.async.wait_group %0;" :: "n"(RS - 2));  // chunk g landed
        __syncthreads();                                          // publish

        if (g + RS - 1 < 8) issue_chunk(smBase, tile, g + RS - 1, tid);
        asm volatile("cp.async.commit_group;");   // one group per iter

        const uint32_t stA = smBase + (g % RS) * STB;
        const uint32_t stW = stA + ACHUNKB;
#pragma unroll
        for (int s = 0; s < 2; s++) {             // two k16 steps per 32-k chunk
            uint32_t b[8];
            uint32_t ba = stW + bRel + s * 1024;
            lds128(b, ba);
            lds128(b + 4, ba ^ 16);
            uint32_t a[2][4];
#pragma unroll
            for (int mt = 0; mt < 2; mt++)
                ldsm_x4(a[mt], stA + aRel[mt] + s * 32);
#pragma unroll
            for (int mt = 0; mt < 2; mt++)
#pragma unroll
                for (int jn = 0; jn < 4; jn++)
                    mma_f16(acc[mt][jn], a[mt], b + jn * 2);
        }
    }

    // epilogue: + bm, store
#pragma unroll
    for (int jn = 0; jn < 4; jn++) {
        int col = warpN * 32 + jn * 8 + 2 * (lane & 3);
        float2 bm2;
        bm2.x = g_bm[col];
        bm2.y = g_bm[col + 1];
#pragma unroll
        for (int mt = 0; mt < 2; mt++) {
            int row = m0 + warpM * 32 + mt * 16 + (lane >> 2);
            if (row < NN) {
                float2 o;
                o.x = acc[mt][jn][0] + bm2.x;
                o.y = acc[mt][jn][1] + bm2.y;
                *(float2*)(out + (size_t)row * DD + col) = o;
            }
            if (row + 8 < NN) {
                float2 o;
                o.x = acc[mt][jn][2] + bm2.x;
                o.y = acc[mt][jn][3] + bm2.y;
                *(float2*)(out + (size_t)(row + 8) * DD + col) = o;
            }
        }
    }
}

// ---------- launcher ----------
extern "C" void kernel_launch(void* const* d_in, const int* in_sizes, int n_in,
                              void* d_out, int out_size) {
    const float* xs = (const float*)d_in[1];   // source_input [N,256]
    const float* Wv = (const float*)d_in[6];
    const float* bv = (const float*)d_in[7];
    float* out = (float*)d_out;

    cudaFuncSetAttribute(vmean_gemm, cudaFuncAttributeMaxDynamicSharedMemorySize, VSMEM);

    prep_kernel<<<128, 256>>>(Wv, bv);
    convA<<<NTILES * 2048 / 256, 256>>>(xs);
    vmean_gemm<<<NTILES, 256, VSMEM>>>(out);
}